// round 13
// baseline (speedup 1.0000x reference)
#include <cuda_runtime.h>

// Problem dims
#define TT 17    // time slices (Tm=16 transitions)
#define DD 128   // nodes
#define HH 256   // input feature dim
#define PP 128   // proj dim
#define EE 32    // edge enc dim
#define MM 128   // msg dim

// ---------------- scratch (device globals; no allocation allowed) ----------
__device__ float g_xT  [TT * DD * HH];   // x transposed: (s,d,h)
__device__ float g_eenc[DD * DD * EE];   // edge encoder output
__device__ float g_henc[TT * DD * PP];   // node encoder output
__device__ float g_Amsg[TT * DD * MM];   // henc @ Wm_h + bm
__device__ float g_Bmsg[DD * DD * MM];   // e_enc @ Wm_e (live pairs only)
__device__ float g_W2c [DD * DD * PP];   // e_enc @ Wc1_c (live pairs only)
__device__ float g_agg [TT * DD * MM];
__device__ float g_hgnn[TT * DD * PP];
__device__ float g_U   [TT * DD * PP];   // hgnn @ Wc1_a + bc1
__device__ float g_V   [TT * DD * PP];   // hgnn @ Wc1_b
__device__ int   g_nbr [DD * DD];
__device__ int   g_ncnt[DD];
__device__ int   g_pairs[DD * DD];
__device__ int   g_npairs;

// ---------------- transpose x (s,h,d) -> (s,d,h) ---------------------------
__global__ void k_transpose(const float* __restrict__ x, float* __restrict__ xT) {
    __shared__ float tile[32][33];
    int s  = blockIdx.z;
    int d0 = blockIdx.x * 32;
    int h0 = blockIdx.y * 32;
    const float* xs = x + s * HH * DD;
    #pragma unroll
    for (int i = threadIdx.y; i < 32; i += 8)
        tile[i][threadIdx.x] = xs[(h0 + i) * DD + d0 + threadIdx.x];
    __syncthreads();
    float* xo = xT + s * DD * HH;
    #pragma unroll
    for (int i = threadIdx.y; i < 32; i += 8)
        xo[(d0 + i) * HH + h0 + threadIdx.x] = tile[threadIdx.x][i];
}

// ---------------- neighbor lists + compacted live-pair list ----------------
// mask[i][j] = (edge_w[i][j] != 0) || (i == j)   (adj values are >= 0)
__global__ void k_nbr(const float* __restrict__ ew) {
    int i = threadIdx.x;  // one thread per node, 1 block of 128
    int c = 0;
    for (int j = 0; j < DD; j++) {
        if (j == i || ew[i * DD + j] != 0.0f) { g_nbr[i * DD + c] = j; c++; }
    }
    g_ncnt[i] = c;
    __shared__ int cnts[DD];
    cnts[i] = c;
    __syncthreads();
    int off = 0;
    for (int j = 0; j < i; j++) off += cnts[j];
    for (int n = 0; n < c; n++) g_pairs[off + n] = i * DD + g_nbr[i * DD + n];
    if (i == DD - 1) g_npairs = off + c;
}

// ---------------- edge encoder: e_enc[i,j,e] = relu(ew[i,j]*We[e]+be[e]) ----
__global__ void k_eenc(const float* __restrict__ ew, const float* __restrict__ We,
                       const float* __restrict__ be) {
    int idx = blockIdx.x * 256 + threadIdx.x;     // over D*D*E = 524288
    int pr = idx >> 5, e = idx & 31;
    g_eenc[idx] = fmaxf(ew[pr] * We[e] + be[e], 0.0f);
}

// ---------------- generic small GEMM: out = act(A @ W + b), N=128 ----------
// CTA: 8 rows x 128 cols, 256 threads (p = tid&127, row-group = tid>>7).
template <int K, int ACT, int HASB>
__global__ void k_gemm(const float* __restrict__ A, const float* __restrict__ W,
                       const float* __restrict__ bias, float* __restrict__ out) {
    __shared__ float sA[8][K];
    const int row0 = blockIdx.x * 8;
    const int tid  = threadIdx.x;
    for (int idx = tid; idx < 8 * K; idx += 256)
        sA[idx / K][idx % K] = A[row0 * K + idx];
    __syncthreads();
    const int p  = tid & 127;
    const int rg = (tid >> 7) * 4;
    float a0, a1, a2, a3;
    if (HASB) { float b = bias[p]; a0 = a1 = a2 = a3 = b; }
    else      { a0 = a1 = a2 = a3 = 0.0f; }
    #pragma unroll 8
    for (int k = 0; k < K; k++) {
        float w = W[k * 128 + p];
        a0 += sA[rg + 0][k] * w;
        a1 += sA[rg + 1][k] * w;
        a2 += sA[rg + 2][k] * w;
        a3 += sA[rg + 3][k] * w;
    }
    if (ACT) { a0 = fmaxf(a0, 0.f); a1 = fmaxf(a1, 0.f); a2 = fmaxf(a2, 0.f); a3 = fmaxf(a3, 0.f); }
    float* o = out + (row0 + rg) * 128 + p;
    o[0] = a0; o[128] = a1; o[256] = a2; o[384] = a3;
}

// ---------------- dual GEMM over live pairs (K=32): Bmsg & W2c -------------
__global__ void k_pair_dual(const float* __restrict__ eenc,
                            const float* __restrict__ W1, const float* __restrict__ W2,
                            float* __restrict__ out1, float* __restrict__ out2) {
    const int npairs = g_npairs;
    const int row0 = blockIdx.x * 8;
    if (row0 >= npairs) return;
    __shared__ float sA[8][EE];
    __shared__ int srow[8];
    const int tid = threadIdx.x;
    if (tid < 8) {
        int rr = row0 + tid;
        srow[tid] = g_pairs[(rr < npairs) ? rr : (npairs - 1)];
    }
    __syncthreads();
    for (int idx = tid; idx < 8 * EE; idx += 256) {
        int r = idx >> 5, k = idx & 31;
        sA[r][k] = eenc[srow[r] * EE + k];
    }
    __syncthreads();
    const int p  = tid & 127;
    const int rg = (tid >> 7) * 4;
    float a0 = 0, a1 = 0, a2 = 0, a3 = 0, b0 = 0, b1 = 0, b2 = 0, b3 = 0;
    #pragma unroll
    for (int k = 0; k < EE; k++) {
        float w1 = W1[k * 128 + p];
        float w2 = W2[k * 128 + p];
        float x0 = sA[rg + 0][k], x1 = sA[rg + 1][k], x2 = sA[rg + 2][k], x3 = sA[rg + 3][k];
        a0 += x0 * w1; a1 += x1 * w1; a2 += x2 * w1; a3 += x3 * w1;
        b0 += x0 * w2; b1 += x1 * w2; b2 += x2 * w2; b3 += x3 * w2;
    }
    #pragma unroll
    for (int i = 0; i < 4; i++) {
        if (row0 + rg + i < npairs) {
            int pr = srow[rg + i];
            float a = (i == 0) ? a0 : (i == 1) ? a1 : (i == 2) ? a2 : a3;
            float b = (i == 0) ? b0 : (i == 1) ? b1 : (i == 2) ? b2 : b3;
            out1[pr * 128 + p] = a;
            out2[pr * 128 + p] = b;
        }
    }
}

// ---------------- aggregation: agg[t,i,m] = max_{j in N(i)} relu(A[t,j,m]+B[i,j,m]) --
// relu folded: values init to 0; unmasked entries contribute exactly 0 in the ref.
__global__ void k_agg() {
    int i = blockIdx.x;
    int m = threadIdx.x;
    int t0 = blockIdx.y * 9;
    int tn = blockIdx.y ? 8 : 9;
    float acc[9];
    #pragma unroll
    for (int t = 0; t < 9; t++) acc[t] = 0.0f;
    int cnt = g_ncnt[i];
    const float* Bi = g_Bmsg + (i * DD) * MM + m;
    for (int n = 0; n < cnt; n++) {
        int j = g_nbr[i * DD + n];
        float b = Bi[j * MM];
        #pragma unroll
        for (int t = 0; t < 9; t++) {
            if (t < tn) {
                float a = g_Amsg[((t0 + t) * DD + j) * MM + m];
                acc[t] = fmaxf(acc[t], a + b);
            }
        }
    }
    #pragma unroll
    for (int t = 0; t < 9; t++)
        if (t < tn) g_agg[((t0 + t) * DD + i) * MM + m] = acc[t];
}

// ---------------- fused GRU-ish update: hgnn = g*relu(cat@Wu+bu)+(1-g)*h ----
__global__ void k_update(const float* __restrict__ henc, const float* __restrict__ agg,
                         const float* __restrict__ Wu, const float* __restrict__ bu,
                         const float* __restrict__ Wg, const float* __restrict__ bg,
                         float* __restrict__ out) {
    __shared__ float sA[8][2 * PP];
    const int row0 = blockIdx.x * 8;
    const int tid  = threadIdx.x;
    for (int idx = tid; idx < 8 * PP; idx += 256) {
        int r = idx >> 7, k = idx & 127;
        sA[r][k]      = henc[(row0 + r) * PP + k];
        sA[r][PP + k] = agg[(row0 + r) * PP + k];
    }
    __syncthreads();
    const int p  = tid & 127;
    const int rg = (tid >> 7) * 4;
    float u0, u1, u2, u3, q0, q1, q2, q3;
    { float b = bu[p]; u0 = u1 = u2 = u3 = b; }
    { float b = bg[p]; q0 = q1 = q2 = q3 = b; }
    #pragma unroll 8
    for (int k = 0; k < 2 * PP; k++) {
        float wu = Wu[k * 128 + p];
        float wg = Wg[k * 128 + p];
        float x0 = sA[rg + 0][k], x1 = sA[rg + 1][k], x2 = sA[rg + 2][k], x3 = sA[rg + 3][k];
        u0 += x0 * wu; u1 += x1 * wu; u2 += x2 * wu; u3 += x3 * wu;
        q0 += x0 * wg; q1 += x1 * wg; q2 += x2 * wg; q3 += x3 * wg;
    }
    float uu[4] = {fmaxf(u0, 0.f), fmaxf(u1, 0.f), fmaxf(u2, 0.f), fmaxf(u3, 0.f)};
    float qq[4] = {q0, q1, q2, q3};
    #pragma unroll
    for (int i = 0; i < 4; i++) {
        float gg = 1.0f / (1.0f + expf(-qq[i]));
        float h  = sA[rg + i][p];
        out[(row0 + rg + i) * 128 + p] = gg * uu[i] + (1.0f - gg) * h;
    }
}

// ---------------- dual GEMM (K=128): U = hgnn@Wc1a + bc1, V = hgnn@Wc1b -----
__global__ void k_uv(const float* __restrict__ hgnn, const float* __restrict__ Wc1,
                     const float* __restrict__ bc1,
                     float* __restrict__ outU, float* __restrict__ outV) {
    __shared__ float sA[8][PP];
    const int row0 = blockIdx.x * 8;
    const int tid  = threadIdx.x;
    for (int idx = tid; idx < 8 * PP; idx += 256)
        sA[idx >> 7][idx & 127] = hgnn[row0 * PP + idx];
    __syncthreads();
    const int p  = tid & 127;
    const int rg = (tid >> 7) * 4;
    const float* Wa = Wc1;
    const float* Wb = Wc1 + 128 * 128;
    float u0, u1, u2, u3, v0 = 0, v1 = 0, v2 = 0, v3 = 0;
    { float b = bc1[p]; u0 = u1 = u2 = u3 = b; }
    #pragma unroll 8
    for (int k = 0; k < PP; k++) {
        float wa = Wa[k * 128 + p];
        float wb = Wb[k * 128 + p];
        float x0 = sA[rg + 0][k], x1 = sA[rg + 1][k], x2 = sA[rg + 2][k], x3 = sA[rg + 3][k];
        u0 += x0 * wa; u1 += x1 * wa; u2 += x2 * wa; u3 += x3 * wa;
        v0 += x0 * wb; v1 += x1 * wb; v2 += x2 * wb; v3 += x3 * wb;
    }
    float* oU = outU + (row0 + rg) * 128 + p;
    float* oV = outV + (row0 + rg) * 128 + p;
    oU[0] = u0; oU[128] = u1; oU[256] = u2; oU[384] = u3;
    oV[0] = v0; oV[128] = v1; oV[256] = v2; oV[384] = v3;
}

// ---------------- logits fill (-1e9 everywhere) -----------------------------
__global__ void k_fill(float* __restrict__ out) {
    out[blockIdx.x * 512 + threadIdx.x] = -1e9f;
}

// ---------------- logits over live pairs ------------------------------------
// logits[t,i,j] = bc2 + sum_p relu(U[t+1,i,p] + V[t,j,p] + W2c[i,j,p]) * Wc2[p]
__global__ void k_logits(const float* __restrict__ Wc2, const float* __restrict__ bc2,
                         float* __restrict__ out) {
    __shared__ float su[16][128];
    __shared__ float sc2[128];
    const int i   = blockIdx.x;
    const int tid = threadIdx.x;
    for (int idx = tid; idx < 16 * 128; idx += 256) {
        int t = idx >> 7, p = idx & 127;
        su[t][p] = g_U[((t + 1) * DD + i) * PP + p];
    }
    if (tid < 128) sc2[tid] = Wc2[tid];
    __syncthreads();
    const int lane = tid & 31, wid = tid >> 5;
    const float b2 = bc2[0];
    const float4 c2 = *(const float4*)&sc2[4 * lane];
    const int cnt = g_ncnt[i];
    for (int n = wid; n < cnt; n += 8) {
        int j = g_nbr[i * DD + n];
        float4 w2 = *(const float4*)&g_W2c[(i * DD + j) * PP + 4 * lane];
        #pragma unroll
        for (int t = 0; t < 16; t++) {
            float4 v = *(const float4*)&g_V[(t * DD + j) * PP + 4 * lane];
            float4 u = *(const float4*)&su[t][4 * lane];
            float s = fmaxf(u.x + v.x + w2.x, 0.f) * c2.x
                    + fmaxf(u.y + v.y + w2.y, 0.f) * c2.y
                    + fmaxf(u.z + v.z + w2.z, 0.f) * c2.z
                    + fmaxf(u.w + v.w + w2.w, 0.f) * c2.w;
            s += __shfl_xor_sync(0xffffffffu, s, 16);
            s += __shfl_xor_sync(0xffffffffu, s, 8);
            s += __shfl_xor_sync(0xffffffffu, s, 4);
            s += __shfl_xor_sync(0xffffffffu, s, 2);
            s += __shfl_xor_sync(0xffffffffu, s, 1);
            if (lane == 0) out[(t * DD + i) * DD + j] = s + b2;
        }
    }
}

// ---------------- dist: (relu([hgnn[t];hgnn[t+1]] @ Wd1 + bd1)) @ Wd2 + bd2 --
__global__ void k_dist(const float* __restrict__ Wd1, const float* __restrict__ bd1,
                       const float* __restrict__ Wd2, const float* __restrict__ bd2,
                       float* __restrict__ out) {
    __shared__ float sh[2 * PP];
    __shared__ float red[4];
    const int t = blockIdx.x >> 7, d = blockIdx.x & 127;
    const int p = threadIdx.x;  // 128 threads
    sh[p]      = g_hgnn[(t * DD + d) * PP + p];
    sh[PP + p] = g_hgnn[((t + 1) * DD + d) * PP + p];
    __syncthreads();
    float acc = bd1[p];
    #pragma unroll 8
    for (int k = 0; k < 2 * PP; k++) acc += sh[k] * Wd1[k * 128 + p];
    acc = fmaxf(acc, 0.0f) * Wd2[p];
    #pragma unroll
    for (int o = 16; o; o >>= 1) acc += __shfl_xor_sync(0xffffffffu, acc, o);
    if ((p & 31) == 0) red[p >> 5] = acc;
    __syncthreads();
    if (p == 0) out[blockIdx.x] = red[0] + red[1] + red[2] + red[3] + bd2[0];
}

// ---------------- host launch ------------------------------------------------
static float* sym(const void* s) {
    void* p = nullptr;
    cudaGetSymbolAddress(&p, s);
    return (float*)p;
}

extern "C" void kernel_launch(void* const* d_in, const int* in_sizes, int n_in,
                              void* d_out, int out_size) {
    const float* x  = (const float*)d_in[0];
    const float* ew = (const float*)d_in[1];
    // Robust to no_graphs scalar being present (index 3, size 1, then time_i size 2)
    int w0 = 5;
    if (!(n_in >= 6 && in_sizes[3] == 1 && in_sizes[4] == 2)) w0 = 4;
    const float* Wn  = (const float*)d_in[w0 + 0];
    const float* bn  = (const float*)d_in[w0 + 1];
    const float* We  = (const float*)d_in[w0 + 2];
    const float* be  = (const float*)d_in[w0 + 3];
    const float* Wm  = (const float*)d_in[w0 + 4];
    const float* bm  = (const float*)d_in[w0 + 5];
    const float* Wu  = (const float*)d_in[w0 + 6];
    const float* bu  = (const float*)d_in[w0 + 7];
    const float* Wg  = (const float*)d_in[w0 + 8];
    const float* bg  = (const float*)d_in[w0 + 9];
    const float* Wc1 = (const float*)d_in[w0 + 10];
    const float* bc1 = (const float*)d_in[w0 + 11];
    const float* Wc2 = (const float*)d_in[w0 + 12];
    const float* bc2 = (const float*)d_in[w0 + 13];
    const float* Wd1 = (const float*)d_in[w0 + 14];
    const float* bd1 = (const float*)d_in[w0 + 15];
    const float* Wd2 = (const float*)d_in[w0 + 16];
    const float* bd2 = (const float*)d_in[w0 + 17];
    float* out = (float*)d_out;

    float* pxT   = sym(g_xT);
    float* peenc = sym(g_eenc);
    float* phenc = sym(g_henc);
    float* pAmsg = sym(g_Amsg);
    float* pBmsg = sym(g_Bmsg);
    float* pW2c  = sym(g_W2c);
    float* pagg  = sym(g_agg);
    float* phgnn = sym(g_hgnn);
    float* pU    = sym(g_U);
    float* pV    = sym(g_V);

    const int ROWS = TT * DD;  // 2176, multiple of 8

    // 1) transpose x -> (s,d,h)
    k_transpose<<<dim3(DD / 32, HH / 32, TT), dim3(32, 8)>>>(x, pxT);
    // 2) adjacency neighbor lists + compact live-pair list
    k_nbr<<<1, DD>>>(ew);
    // 3) edge encoder
    k_eenc<<<(DD * DD * EE) / 256, 256>>>(ew, We, be);
    // 4) node encoder: henc = relu(xT @ Wn + bn)
    k_gemm<HH, 1, 1><<<ROWS / 8, 256>>>(pxT, Wn, bn, phenc);
    // 5) A-part of messages: Amsg = henc @ Wm[0:128] + bm
    k_gemm<PP, 0, 1><<<ROWS / 8, 256>>>(phenc, Wm, bm, pAmsg);
    // 6) B-part of messages + edge part of classifier, live pairs only
    k_pair_dual<<<(DD * DD) / 8, 256>>>(peenc, Wm + 128 * 128, Wc1 + 256 * 128,
                                        pBmsg, pW2c);
    // 7) max-aggregation
    k_agg<<<dim3(DD, 2), MM>>>();
    // 8) gated update -> hgnn
    k_update<<<ROWS / 8, 256>>>(phenc, pagg, Wu, bu, Wg, bg, phgnn);
    // 9) classifier node parts: U = hgnn@Wc1a + bc1, V = hgnn@Wc1b
    k_uv<<<ROWS / 8, 256>>>(phgnn, Wc1, bc1, pU, pV);
    // 10) logits: fill -1e9, then compute live pairs
    k_fill<<<(16 * DD * DD) / 512, 512>>>(out);
    k_logits<<<DD, 256>>>(Wc2, bc2, out);
    // 11) dist head
    k_dist<<<16 * DD, 128>>>(Wd1, bd1, Wd2, bd2, out + 16 * DD * DD);
}